// round 1
// baseline (speedup 1.0000x reference)
#include <cuda_runtime.h>
#include <cuda_bf16.h>

// RandomResizedCrop: crop audio[start : start+crop_len], then linear-interp
// resample back to original length n (= out_size = 2^25).
//
// idx must replicate float32 jnp.linspace(0, crop_len-1, n) = f32(i) * delta,
// delta = f32(crop_len-1) / f32(n-1)  (== 0.875f exactly for these shapes).
// CUDA's RN int->float convert + RN f32 multiply match XLA's, so lo/w agree
// bit-for-bit with the reference.

__global__ __launch_bounds__(256)
void resample_kernel(const float* __restrict__ audio,
                     const int* __restrict__ p_crop,
                     const int* __restrict__ p_start,
                     float* __restrict__ out,
                     int n) {
    const int crop_len = __ldg(p_crop);
    const int start    = __ldg(p_start);
    const float delta  = (float)(crop_len - 1) / (float)(n - 1);
    const int hi_clamp = crop_len - 1;
    const float* __restrict__ base = audio + start;

    int i0 = (blockIdx.x * blockDim.x + threadIdx.x) * 4;
    if (i0 >= n) return;

    float v[4];
    #pragma unroll
    for (int k = 0; k < 4; k++) {
        int i      = i0 + k;
        float fi   = (float)i;          // RN convert, rounds for i > 2^24 (matches f32 iota)
        float idx  = fi * delta;        // RN f32 multiply (matches XLA linspace)
        int lo     = (int)floorf(idx);
        int hi     = min(lo + 1, hi_clamp);
        float w    = idx - (float)lo;
        float a    = __ldg(base + lo);
        float b    = __ldg(base + hi);
        v[k] = (1.0f - w) * a + w * b;
    }

    // n = 2^25 is a multiple of 4 and i0 is 4-element aligned -> safe float4 store
    float4 r = make_float4(v[0], v[1], v[2], v[3]);
    *reinterpret_cast<float4*>(out + i0) = r;
}

extern "C" void kernel_launch(void* const* d_in, const int* in_sizes, int n_in,
                              void* d_out, int out_size) {
    const float* audio  = (const float*)d_in[0];
    const int*   p_crop = (const int*)d_in[1];
    const int*   p_start= (const int*)d_in[2];
    float*       out    = (float*)d_out;

    const int n = out_size;                 // original_len = 2^25
    const int threads = 256;
    const int elems_per_thread = 4;
    const int blocks = (n + threads * elems_per_thread - 1) / (threads * elems_per_thread);

    resample_kernel<<<blocks, threads>>>(audio, p_crop, p_start, out, n);
}